// round 8
// baseline (speedup 1.0000x reference)
#include <cuda_runtime.h>
#include <math.h>

#define NN 262144
#define LL 64
#define LOG_L 6
#define CC (NN / LL)      // 4096 chunks of 64 steps
#define MM 2048
#define GRAV 9.81007f
#define WALL 0xffffffffu
#define NBLK 512
#define NTHR 256

struct S12 { float4 dq; float Ax,Ay,Az,Px,Py,Pz,T,G; };

__device__ float4 g_s0[CC];      // chunk totals: dq
__device__ float4 g_s1[CC];      // Ax,Ay,Az,T
__device__ float4 g_s2[CC];      // Px,Py,Pz,G
__device__ float4 g_sq[CC];      // chunk-start world rotation
__device__ float  g_sv[3 * CC];
__device__ float  g_sp[3 * CC];
__device__ double g_part[2 * MM];
__device__ volatile unsigned g_gen = 0;
__device__ unsigned g_cnt = 0;

// ---------------- grid barrier (co-residency guaranteed by launch_bounds) ----------------
__device__ __forceinline__ void grid_bar() {
    __syncthreads();
    if (threadIdx.x == 0) {
        __threadfence();
        unsigned g = g_gen;
        if (atomicAdd(&g_cnt, 1u) == NBLK - 1) {
            g_cnt = 0;
            __threadfence();
            g_gen = g + 1;
        } else {
            while (g_gen == g) __nanosleep(64);
        }
        __threadfence();
    }
    __syncthreads();
}

// ---------------- quaternion helpers ----------------
__device__ __forceinline__ float4 qmul4(float4 q, float4 r) {
    return make_float4(
        q.w*r.x + q.x*r.w + q.y*r.z - q.z*r.y,
        q.w*r.y - q.x*r.z + q.y*r.w + q.z*r.x,
        q.w*r.z + q.x*r.y - q.y*r.x + q.z*r.w,
        q.w*r.w - q.x*r.x - q.y*r.y - q.z*r.z);
}
__device__ __forceinline__ float4 qnorm4(float4 q) {
    float n = rsqrtf(q.x*q.x + q.y*q.y + q.z*q.z + q.w*q.w);
    return make_float4(q.x*n, q.y*n, q.z*n, q.w*n);
}
__device__ __forceinline__ float3 qrot3(float4 q, float3 v) {
    float tx = 2.0f*(q.y*v.z - q.z*v.y);
    float ty = 2.0f*(q.z*v.x - q.x*v.z);
    float tz = 2.0f*(q.x*v.y - q.y*v.x);
    return make_float3(
        v.x + q.w*tx + (q.y*tz - q.z*ty),
        v.y + q.w*ty + (q.z*tx - q.x*tz),
        v.z + q.w*tz + (q.x*ty - q.y*tx));
}

// ---------------- summary algebra ----------------
__device__ __forceinline__ S12 sident() {
    S12 s; s.dq = make_float4(0.f,0.f,0.f,1.f);
    s.Ax=s.Ay=s.Az=s.Px=s.Py=s.Pz=0.f; s.T=s.G=0.f; return s;
}
__device__ __forceinline__ S12 scomb(const S12& a, const S12& b) {
    S12 o;
    o.T = a.T + b.T;
    o.G = a.G + a.T*b.T + b.G;
    float3 rA = qrot3(a.dq, make_float3(b.Ax, b.Ay, b.Az));
    o.Ax = a.Ax + rA.x;  o.Ay = a.Ay + rA.y;  o.Az = a.Az + rA.z;
    float3 rP = qrot3(a.dq, make_float3(b.Px, b.Py, b.Pz));
    o.Px = a.Px + a.Ax*b.T + rP.x;
    o.Py = a.Py + a.Ay*b.T + rP.y;
    o.Pz = a.Pz + a.Az*b.T + rP.z;
    o.dq = qmul4(a.dq, b.dq);
    return o;
}
__device__ __forceinline__ S12 shfl_down_S(const S12& s, int off) {
    S12 r;
    r.dq.x = __shfl_down_sync(WALL, s.dq.x, off);
    r.dq.y = __shfl_down_sync(WALL, s.dq.y, off);
    r.dq.z = __shfl_down_sync(WALL, s.dq.z, off);
    r.dq.w = __shfl_down_sync(WALL, s.dq.w, off);
    r.Ax = __shfl_down_sync(WALL, s.Ax, off);
    r.Ay = __shfl_down_sync(WALL, s.Ay, off);
    r.Az = __shfl_down_sync(WALL, s.Az, off);
    r.Px = __shfl_down_sync(WALL, s.Px, off);
    r.Py = __shfl_down_sync(WALL, s.Py, off);
    r.Pz = __shfl_down_sync(WALL, s.Pz, off);
    r.T  = __shfl_down_sync(WALL, s.T,  off);
    r.G  = __shfl_down_sync(WALL, s.G,  off);
    return r;
}
__device__ __forceinline__ S12 shfl_up_S(const S12& s, int off) {
    S12 r;
    r.dq.x = __shfl_up_sync(WALL, s.dq.x, off);
    r.dq.y = __shfl_up_sync(WALL, s.dq.y, off);
    r.dq.z = __shfl_up_sync(WALL, s.dq.z, off);
    r.dq.w = __shfl_up_sync(WALL, s.dq.w, off);
    r.Ax = __shfl_up_sync(WALL, s.Ax, off);
    r.Ay = __shfl_up_sync(WALL, s.Ay, off);
    r.Az = __shfl_up_sync(WALL, s.Az, off);
    r.Px = __shfl_up_sync(WALL, s.Px, off);
    r.Py = __shfl_up_sync(WALL, s.Py, off);
    r.Pz = __shfl_up_sync(WALL, s.Pz, off);
    r.T  = __shfl_up_sync(WALL, s.T,  off);
    r.G  = __shfl_up_sync(WALL, s.G,  off);
    return r;
}
__device__ __forceinline__ S12 warp_fold(S12 s) {
#pragma unroll
    for (int off = 1; off < 32; off <<= 1) s = scomb(s, shfl_down_S(s, off));
    return s;  // lane 0
}
__device__ __forceinline__ S12 warp_scan(S12 s, int lane) {
#pragma unroll
    for (int off = 1; off < 32; off <<= 1) {
        S12 o = shfl_up_S(s, off);
        if (lane >= off) s = scomb(o, s);
    }
    return s;
}

// per-step summary (Taylor exp_so3; guarded libm fallback)
__device__ __forceinline__ S12 step_reg(float ax, float ay, float az,
                                        float gx, float gy, float gz, float dt,
                                        float abx, float aby, float abz,
                                        float gbx, float gby, float gbz) {
    ax -= abx; ay -= aby; az -= abz;
    float px = (gx - gbx) * dt;
    float py = (gy - gby) * dt;
    float pz = (gz - gbz) * dt;
    float th2 = px*px + py*py + pz*pz;
    float h2 = 0.25f * th2;
    float sc, w;
    if (h2 < 0.04f) {
        sc = 1.0f - h2*(1.0f/6.0f)*(1.0f - h2*0.05f);
        w  = 1.0f - h2*0.5f*(1.0f - h2*(1.0f/12.0f));
    } else {
        float half = sqrtf(h2);
        sc = sinf(half) / half;
        w  = cosf(half);
    }
    float k = 0.5f * sc;
    S12 s;
    s.dq = make_float4(px*k, py*k, pz*k, w);
    float h = 0.5f * dt * dt;
    s.T = dt;  s.G = h;
    s.Ax = ax*dt;  s.Ay = ay*dt;  s.Az = az*dt;
    s.Px = ax*h;   s.Py = ay*h;   s.Pz = az*h;
    return s;
}
__device__ __forceinline__ S12 load_chunk(int c) {
    float4 f0 = g_s0[c], f1 = g_s1[c], f2 = g_s2[c];
    S12 s; s.dq=f0; s.Ax=f1.x; s.Ay=f1.y; s.Az=f1.z; s.T=f1.w;
    s.Px=f2.x; s.Py=f2.y; s.Pz=f2.z; s.G=f2.w;
    return s;
}

// ---------------- the one persistent kernel ----------------
__global__ void __launch_bounds__(NTHR, 4)
k_all(const float* __restrict__ acc, const float* __restrict__ gyr,
      const float* __restrict__ ab,  const float* __restrict__ gb,
      const float* __restrict__ dts,
      const float* __restrict__ q0p, const float* __restrict__ p0p,
      const float* __restrict__ v0p,
      const float* __restrict__ prot, const float* __restrict__ ptrn,
      const int* __restrict__ sync, float* __restrict__ out) {
    __shared__ S12 shw[8];
    __shared__ double red1[8], red2[8];
    int lane = threadIdx.x & 31;
    int wid  = threadIdx.x >> 5;
    int gw   = blockIdx.x * (NTHR/32) + wid;     // global warp id, [0, 4096)
    float abx = __ldg(&ab[0]), aby = __ldg(&ab[1]), abz = __ldg(&ab[2]);
    float gbx = __ldg(&gb[0]), gby = __ldg(&gb[1]), gbz = __ldg(&gb[2]);
    const float2* acc2 = (const float2*)acc;
    const float2* gyr2 = (const float2*)gyr;
    const float2* dt2  = (const float2*)dts;

    // ===== Phase A: chunk summaries (warp <-> chunk, serial-2 per lane) =====
    {
        int vb = 96*gw + 3*lane;
        float2 A0 = acc2[vb], A1 = acc2[vb+1], A2 = acc2[vb+2];
        float2 G0 = gyr2[vb], G1 = gyr2[vb+1], G2 = gyr2[vb+2];
        float2 D  = dt2[(gw<<5) + lane];
        S12 s =      step_reg(A0.x,A0.y,A1.x, G0.x,G0.y,G1.x, D.x, abx,aby,abz, gbx,gby,gbz);
        s = scomb(s, step_reg(A1.y,A2.x,A2.y, G1.y,G2.x,G2.y, D.y, abx,aby,abz, gbx,gby,gbz));
        s = warp_fold(s);
        if (lane == 0) {
            s.dq = qnorm4(s.dq);
            g_s0[gw] = s.dq;
            g_s1[gw] = make_float4(s.Ax, s.Ay, s.Az, s.T);
            g_s2[gw] = make_float4(s.Px, s.Py, s.Pz, s.G);
        }
    }
    grid_bar();

    // ===== Phase B: CTA 0 scans 4096 chunk summaries -> chunk-start states =====
    if (blockIdx.x == 0) {
        int t = threadIdx.x;
        int c0 = 16*t;
        S12 tot = load_chunk(c0);
#pragma unroll 4
        for (int k = 1; k < 16; k++) tot = scomb(tot, load_chunk(c0 + k));
        S12 inc = warp_scan(tot, lane);
        if (lane == 31) shw[wid] = inc;
        __syncthreads();
        if (wid == 0) {
            // ALL 32 lanes participate in shuffles; lanes >= 8 carry identity.
            S12 v = (lane < 8) ? shw[lane] : sident();
#pragma unroll
            for (int off = 1; off < 8; off <<= 1) {
                S12 o = shfl_up_S(v, off);
                if (lane >= off && lane < 8) v = scomb(o, v);
            }
            if (lane < 8) shw[lane] = v;
        }
        __syncthreads();
        S12 lex = shfl_up_S(inc, 1);
        S12 ex;
        if (wid == 0) ex = (lane == 0) ? sident() : lex;
        else          ex = (lane == 0) ? shw[wid-1] : scomb(shw[wid-1], lex);

        float4 q0 = make_float4(q0p[0], q0p[1], q0p[2], q0p[3]);
        float3 v0 = make_float3(v0p[0], v0p[1], v0p[2]);
        float3 p0 = make_float3(p0p[0], p0p[1], p0p[2]);
        for (int k = 0; k < 16; k++) {
            int c = c0 + k;
            float4 qc = qnorm4(qmul4(q0, ex.dq));
            float3 rA = qrot3(q0, make_float3(ex.Ax, ex.Ay, ex.Az));
            float3 rP = qrot3(q0, make_float3(ex.Px, ex.Py, ex.Pz));
            g_sq[c] = qc;
            g_sv[3*c]   = v0.x + rA.x;
            g_sv[3*c+1] = v0.y + rA.y;
            g_sv[3*c+2] = v0.z + rA.z - GRAV * ex.T;
            g_sp[3*c]   = p0.x + v0.x * ex.T + rP.x;
            g_sp[3*c+1] = p0.y + v0.y * ex.T + rP.y;
            g_sp[3*c+2] = p0.z + v0.z * ex.T + rP.z - GRAV * ex.G;
            if (k < 15) ex = scomb(ex, load_chunk(c));
        }
    }
    grid_bar();

    // ===== Phase C: sync-point evaluation (warp <-> sync point) =====
    if (gw < MM) {     // warp-uniform predicate: shuffles inside are safe
        int i = sync[gw];
        int c = i >> LOG_L;
        int r = i & (LL - 1);
        int vb = 96*c + 3*lane;
        S12 s = sident();
        int j0 = 2*lane, j1 = 2*lane + 1;
        if (j0 <= r) {
            float2 A0 = acc2[vb], A1 = acc2[vb+1];
            float2 G0 = gyr2[vb], G1 = gyr2[vb+1];
            float2 D  = dt2[(c<<5) + lane];
            s = step_reg(A0.x,A0.y,A1.x, G0.x,G0.y,G1.x, D.x, abx,aby,abz, gbx,gby,gbz);
            if (j1 <= r) {
                float2 A2 = acc2[vb+2];
                float2 G2 = gyr2[vb+2];
                s = scomb(s, step_reg(A1.y,A2.x,A2.y, G1.y,G2.x,G2.y, D.y, abx,aby,abz, gbx,gby,gbz));
            }
        }
        s = warp_fold(s);
        if (lane == 0) {
            float4 qc = g_sq[c];
            float4 q = qnorm4(qmul4(qc, s.dq));
            float tel = s.T;
            float3 rP = qrot3(qc, make_float3(s.Px, s.Py, s.Pz));
            float Pxx = g_sp[3*c]   + g_sv[3*c]  * tel + rP.x;
            float Pyy = g_sp[3*c+1] + g_sv[3*c+1]* tel + rP.y;
            float Pzz = g_sp[3*c+2] + g_sv[3*c+2]* tel + rP.z - GRAV * s.G;

            float4 pq = make_float4(prot[4*gw], prot[4*gw+1], prot[4*gw+2], prot[4*gw+3]);
            float4 rel = qmul4(make_float4(-pq.x, -pq.y, -pq.z, pq.w), q);
            float nn2 = rel.x*rel.x + rel.y*rel.y + rel.z*rel.z;
            float nn = sqrtf(nn2);
            float theta = 2.0f * atan2f(nn, rel.w);
            float scale = (nn < 1e-7f) ? 2.0f : theta / fmaxf(nn, 1e-12f);
            float lsq = nn2 * scale * scale;

            float dx = ptrn[3*gw+0] - Pxx;
            float dy = ptrn[3*gw+1] - Pyy;
            float dz = ptrn[3*gw+2] - Pzz;
            g_part[gw]      = (double)lsq;
            g_part[MM + gw] = (double)dx*dx + (double)dy*dy + (double)dz*dz;
        }
    }
    grid_bar();

    // ===== Phase D: CTA 0 deterministic reduction =====
    if (blockIdx.x == 0) {
        int t = threadIdx.x;
        double s1 = 0.0, s2 = 0.0;
#pragma unroll
        for (int k = 0; k < 8; k++) {
            s1 += g_part[t + 256*k];
            s2 += g_part[MM + t + 256*k];
        }
#pragma unroll
        for (int off = 16; off > 0; off >>= 1) {
            s1 += __shfl_down_sync(WALL, s1, off);
            s2 += __shfl_down_sync(WALL, s2, off);
        }
        if (lane == 0) { red1[wid] = s1; red2[wid] = s2; }
        __syncthreads();
        if (t == 0) {
            double a = 0.0, b = 0.0;
#pragma unroll
            for (int k = 0; k < 8; k++) { a += red1[k]; b += red2[k]; }
            out[0] = (float)(sqrt(a) + b / (3.0 * (double)MM));
        }
    }
}

// ---------------- launch ----------------
extern "C" void kernel_launch(void* const* d_in, const int* in_sizes, int n_in,
                              void* d_out, int out_size) {
    const float* acc  = (const float*)d_in[0];
    const float* gyr  = (const float*)d_in[1];
    const float* ab   = (const float*)d_in[2];
    const float* gb   = (const float*)d_in[3];
    const float* dts  = (const float*)d_in[4];
    const float* q0   = (const float*)d_in[5];
    const float* p0   = (const float*)d_in[6];
    const float* v0   = (const float*)d_in[7];
    const float* prot = (const float*)d_in[8];
    const float* ptrn = (const float*)d_in[9];
    const int*   sync = (const int*)d_in[10];

    k_all<<<NBLK, NTHR>>>(acc, gyr, ab, gb, dts, q0, p0, v0,
                          prot, ptrn, sync, (float*)d_out);
}

// round 9
// speedup vs baseline: 1.0050x; 1.0050x over previous
#include <cuda_runtime.h>
#include <math.h>

#define NN 262144
#define LL 64
#define LOG_L 6
#define CC (NN / LL)      // 4096 chunks of 64 steps
#define MM 2048
#define GRAV 9.81007f
#define WALL 0xffffffffu
#define NBLK 512
#define NTHR 256

struct S12 { float4 dq; float Ax,Ay,Az,Px,Py,Pz,T,G; };

__device__ float4 g_s0[CC];      // chunk totals: dq
__device__ float4 g_s1[CC];      // Ax,Ay,Az,T
__device__ float4 g_s2[CC];      // Px,Py,Pz,G
__device__ float4 g_sq[CC];      // chunk-start world rotation
__device__ float  g_sv[3 * CC];
__device__ float  g_sp[3 * CC];
__device__ double g_part[2 * MM];
__device__ volatile unsigned g_gen = 0;
__device__ unsigned g_cnt = 0;

// ---------------- grid barrier (co-residency guaranteed by launch_bounds) ----------------
__device__ __forceinline__ void grid_bar() {
    __syncthreads();
    if (threadIdx.x == 0) {
        __threadfence();
        unsigned g = g_gen;
        if (atomicAdd(&g_cnt, 1u) == NBLK - 1) {
            g_cnt = 0;
            __threadfence();
            g_gen = g + 1;
        } else {
            while (g_gen == g) __nanosleep(64);
        }
        __threadfence();
    }
    __syncthreads();
}

// ---------------- quaternion helpers ----------------
__device__ __forceinline__ float4 qmul4(float4 q, float4 r) {
    return make_float4(
        q.w*r.x + q.x*r.w + q.y*r.z - q.z*r.y,
        q.w*r.y - q.x*r.z + q.y*r.w + q.z*r.x,
        q.w*r.z + q.x*r.y - q.y*r.x + q.z*r.w,
        q.w*r.w - q.x*r.x - q.y*r.y - q.z*r.z);
}
__device__ __forceinline__ float4 qnorm4(float4 q) {
    float n = rsqrtf(q.x*q.x + q.y*q.y + q.z*q.z + q.w*q.w);
    return make_float4(q.x*n, q.y*n, q.z*n, q.w*n);
}
__device__ __forceinline__ float3 qrot3(float4 q, float3 v) {
    float tx = 2.0f*(q.y*v.z - q.z*v.y);
    float ty = 2.0f*(q.z*v.x - q.x*v.z);
    float tz = 2.0f*(q.x*v.y - q.y*v.x);
    return make_float3(
        v.x + q.w*tx + (q.y*tz - q.z*ty),
        v.y + q.w*ty + (q.z*tx - q.x*tz),
        v.z + q.w*tz + (q.x*ty - q.y*tx));
}

// ---------------- summary algebra ----------------
__device__ __forceinline__ S12 sident() {
    S12 s; s.dq = make_float4(0.f,0.f,0.f,1.f);
    s.Ax=s.Ay=s.Az=s.Px=s.Py=s.Pz=0.f; s.T=s.G=0.f; return s;
}
__device__ __forceinline__ S12 scomb(const S12& a, const S12& b) {
    S12 o;
    o.T = a.T + b.T;
    o.G = a.G + a.T*b.T + b.G;
    float3 rA = qrot3(a.dq, make_float3(b.Ax, b.Ay, b.Az));
    o.Ax = a.Ax + rA.x;  o.Ay = a.Ay + rA.y;  o.Az = a.Az + rA.z;
    float3 rP = qrot3(a.dq, make_float3(b.Px, b.Py, b.Pz));
    o.Px = a.Px + a.Ax*b.T + rP.x;
    o.Py = a.Py + a.Ay*b.T + rP.y;
    o.Pz = a.Pz + a.Az*b.T + rP.z;
    o.dq = qmul4(a.dq, b.dq);
    return o;
}
__device__ __forceinline__ S12 shfl_down_S(const S12& s, int off) {
    S12 r;
    r.dq.x = __shfl_down_sync(WALL, s.dq.x, off);
    r.dq.y = __shfl_down_sync(WALL, s.dq.y, off);
    r.dq.z = __shfl_down_sync(WALL, s.dq.z, off);
    r.dq.w = __shfl_down_sync(WALL, s.dq.w, off);
    r.Ax = __shfl_down_sync(WALL, s.Ax, off);
    r.Ay = __shfl_down_sync(WALL, s.Ay, off);
    r.Az = __shfl_down_sync(WALL, s.Az, off);
    r.Px = __shfl_down_sync(WALL, s.Px, off);
    r.Py = __shfl_down_sync(WALL, s.Py, off);
    r.Pz = __shfl_down_sync(WALL, s.Pz, off);
    r.T  = __shfl_down_sync(WALL, s.T,  off);
    r.G  = __shfl_down_sync(WALL, s.G,  off);
    return r;
}
__device__ __forceinline__ S12 shfl_up_S(const S12& s, int off) {
    S12 r;
    r.dq.x = __shfl_up_sync(WALL, s.dq.x, off);
    r.dq.y = __shfl_up_sync(WALL, s.dq.y, off);
    r.dq.z = __shfl_up_sync(WALL, s.dq.z, off);
    r.dq.w = __shfl_up_sync(WALL, s.dq.w, off);
    r.Ax = __shfl_up_sync(WALL, s.Ax, off);
    r.Ay = __shfl_up_sync(WALL, s.Ay, off);
    r.Az = __shfl_up_sync(WALL, s.Az, off);
    r.Px = __shfl_up_sync(WALL, s.Px, off);
    r.Py = __shfl_up_sync(WALL, s.Py, off);
    r.Pz = __shfl_up_sync(WALL, s.Pz, off);
    r.T  = __shfl_up_sync(WALL, s.T,  off);
    r.G  = __shfl_up_sync(WALL, s.G,  off);
    return r;
}
__device__ __forceinline__ S12 warp_fold(S12 s) {
#pragma unroll
    for (int off = 1; off < 32; off <<= 1) s = scomb(s, shfl_down_S(s, off));
    return s;  // lane 0
}
__device__ __forceinline__ S12 warp_scan(S12 s, int lane) {
#pragma unroll
    for (int off = 1; off < 32; off <<= 1) {
        S12 o = shfl_up_S(s, off);
        if (lane >= off) s = scomb(o, s);
    }
    return s;
}

// per-step summary (Taylor exp_so3; guarded libm fallback)
__device__ __forceinline__ S12 step_reg(float ax, float ay, float az,
                                        float gx, float gy, float gz, float dt,
                                        float abx, float aby, float abz,
                                        float gbx, float gby, float gbz) {
    ax -= abx; ay -= aby; az -= abz;
    float px = (gx - gbx) * dt;
    float py = (gy - gby) * dt;
    float pz = (gz - gbz) * dt;
    float th2 = px*px + py*py + pz*pz;
    float h2 = 0.25f * th2;
    float sc, w;
    if (h2 < 0.04f) {
        sc = 1.0f - h2*(1.0f/6.0f)*(1.0f - h2*0.05f);
        w  = 1.0f - h2*0.5f*(1.0f - h2*(1.0f/12.0f));
    } else {
        float half = sqrtf(h2);
        sc = sinf(half) / half;
        w  = cosf(half);
    }
    float k = 0.5f * sc;
    S12 s;
    s.dq = make_float4(px*k, py*k, pz*k, w);
    float h = 0.5f * dt * dt;
    s.T = dt;  s.G = h;
    s.Ax = ax*dt;  s.Ay = ay*dt;  s.Az = az*dt;
    s.Px = ax*h;   s.Py = ay*h;   s.Pz = az*h;
    return s;
}
__device__ __forceinline__ S12 load_chunk(int c) {
    float4 f0 = g_s0[c], f1 = g_s1[c], f2 = g_s2[c];
    S12 s; s.dq=f0; s.Ax=f1.x; s.Ay=f1.y; s.Az=f1.z; s.T=f1.w;
    s.Px=f2.x; s.Py=f2.y; s.Pz=f2.z; s.G=f2.w;
    return s;
}

// ---------------- the one persistent kernel ----------------
__global__ void __launch_bounds__(NTHR, 4)
k_all(const float* __restrict__ acc, const float* __restrict__ gyr,
      const float* __restrict__ ab,  const float* __restrict__ gb,
      const float* __restrict__ dts,
      const float* __restrict__ q0p, const float* __restrict__ p0p,
      const float* __restrict__ v0p,
      const float* __restrict__ prot, const float* __restrict__ ptrn,
      const int* __restrict__ sync, float* __restrict__ out) {
    __shared__ S12 shw[8];
    __shared__ double red1[8], red2[8];
    int lane = threadIdx.x & 31;
    int wid  = threadIdx.x >> 5;
    int gw   = blockIdx.x * (NTHR/32) + wid;     // global warp id, [0, 4096)
    float abx = __ldg(&ab[0]), aby = __ldg(&ab[1]), abz = __ldg(&ab[2]);
    float gbx = __ldg(&gb[0]), gby = __ldg(&gb[1]), gbz = __ldg(&gb[2]);
    const float2* acc2 = (const float2*)acc;
    const float2* gyr2 = (const float2*)gyr;
    const float2* dt2  = (const float2*)dts;

    // ===== Phase A: chunk summaries (warp <-> chunk, serial-2 per lane) =====
    {
        int vb = 96*gw + 3*lane;
        float2 A0 = acc2[vb], A1 = acc2[vb+1], A2 = acc2[vb+2];
        float2 G0 = gyr2[vb], G1 = gyr2[vb+1], G2 = gyr2[vb+2];
        float2 D  = dt2[(gw<<5) + lane];
        S12 s =      step_reg(A0.x,A0.y,A1.x, G0.x,G0.y,G1.x, D.x, abx,aby,abz, gbx,gby,gbz);
        s = scomb(s, step_reg(A1.y,A2.x,A2.y, G1.y,G2.x,G2.y, D.y, abx,aby,abz, gbx,gby,gbz));
        s = warp_fold(s);
        if (lane == 0) {
            s.dq = qnorm4(s.dq);
            g_s0[gw] = s.dq;
            g_s1[gw] = make_float4(s.Ax, s.Ay, s.Az, s.T);
            g_s2[gw] = make_float4(s.Px, s.Py, s.Pz, s.G);
        }
    }
    grid_bar();

    // ===== Phase B: CTA 0 scans 4096 chunk summaries -> chunk-start states =====
    if (blockIdx.x == 0) {
        int t = threadIdx.x;
        int c0 = 16*t;
        S12 tot = load_chunk(c0);
#pragma unroll 4
        for (int k = 1; k < 16; k++) tot = scomb(tot, load_chunk(c0 + k));
        S12 inc = warp_scan(tot, lane);
        if (lane == 31) shw[wid] = inc;
        __syncthreads();
        if (wid == 0) {
            // ALL 32 lanes participate in shuffles; lanes >= 8 carry identity.
            S12 v = (lane < 8) ? shw[lane] : sident();
#pragma unroll
            for (int off = 1; off < 8; off <<= 1) {
                S12 o = shfl_up_S(v, off);
                if (lane >= off && lane < 8) v = scomb(o, v);
            }
            if (lane < 8) shw[lane] = v;
        }
        __syncthreads();
        S12 lex = shfl_up_S(inc, 1);
        S12 ex;
        if (wid == 0) ex = (lane == 0) ? sident() : lex;
        else          ex = (lane == 0) ? shw[wid-1] : scomb(shw[wid-1], lex);

        float4 q0 = make_float4(q0p[0], q0p[1], q0p[2], q0p[3]);
        float3 v0 = make_float3(v0p[0], v0p[1], v0p[2]);
        float3 p0 = make_float3(p0p[0], p0p[1], p0p[2]);
        for (int k = 0; k < 16; k++) {
            int c = c0 + k;
            float4 qc = qnorm4(qmul4(q0, ex.dq));
            float3 rA = qrot3(q0, make_float3(ex.Ax, ex.Ay, ex.Az));
            float3 rP = qrot3(q0, make_float3(ex.Px, ex.Py, ex.Pz));
            g_sq[c] = qc;
            g_sv[3*c]   = v0.x + rA.x;
            g_sv[3*c+1] = v0.y + rA.y;
            g_sv[3*c+2] = v0.z + rA.z - GRAV * ex.T;
            g_sp[3*c]   = p0.x + v0.x * ex.T + rP.x;
            g_sp[3*c+1] = p0.y + v0.y * ex.T + rP.y;
            g_sp[3*c+2] = p0.z + v0.z * ex.T + rP.z - GRAV * ex.G;
            if (k < 15) ex = scomb(ex, load_chunk(c));
        }
    }
    grid_bar();

    // ===== Phase C: sync-point evaluation (warp <-> sync point) =====
    if (gw < MM) {     // warp-uniform predicate: shuffles inside are safe
        int i = sync[gw];
        int c = i >> LOG_L;
        int r = i & (LL - 1);
        int vb = 96*c + 3*lane;
        S12 s = sident();
        int j0 = 2*lane, j1 = 2*lane + 1;
        if (j0 <= r) {
            float2 A0 = acc2[vb], A1 = acc2[vb+1];
            float2 G0 = gyr2[vb], G1 = gyr2[vb+1];
            float2 D  = dt2[(c<<5) + lane];
            s = step_reg(A0.x,A0.y,A1.x, G0.x,G0.y,G1.x, D.x, abx,aby,abz, gbx,gby,gbz);
            if (j1 <= r) {
                float2 A2 = acc2[vb+2];
                float2 G2 = gyr2[vb+2];
                s = scomb(s, step_reg(A1.y,A2.x,A2.y, G1.y,G2.x,G2.y, D.y, abx,aby,abz, gbx,gby,gbz));
            }
        }
        s = warp_fold(s);
        if (lane == 0) {
            float4 qc = g_sq[c];
            float4 q = qnorm4(qmul4(qc, s.dq));
            float tel = s.T;
            float3 rP = qrot3(qc, make_float3(s.Px, s.Py, s.Pz));
            float Pxx = g_sp[3*c]   + g_sv[3*c]  * tel + rP.x;
            float Pyy = g_sp[3*c+1] + g_sv[3*c+1]* tel + rP.y;
            float Pzz = g_sp[3*c+2] + g_sv[3*c+2]* tel + rP.z - GRAV * s.G;

            float4 pq = make_float4(prot[4*gw], prot[4*gw+1], prot[4*gw+2], prot[4*gw+3]);
            float4 rel = qmul4(make_float4(-pq.x, -pq.y, -pq.z, pq.w), q);
            float nn2 = rel.x*rel.x + rel.y*rel.y + rel.z*rel.z;
            float nn = sqrtf(nn2);
            float theta = 2.0f * atan2f(nn, rel.w);
            float scale = (nn < 1e-7f) ? 2.0f : theta / fmaxf(nn, 1e-12f);
            float lsq = nn2 * scale * scale;

            float dx = ptrn[3*gw+0] - Pxx;
            float dy = ptrn[3*gw+1] - Pyy;
            float dz = ptrn[3*gw+2] - Pzz;
            g_part[gw]      = (double)lsq;
            g_part[MM + gw] = (double)dx*dx + (double)dy*dy + (double)dz*dz;
        }
    }
    grid_bar();

    // ===== Phase D: CTA 0 deterministic reduction =====
    if (blockIdx.x == 0) {
        int t = threadIdx.x;
        double s1 = 0.0, s2 = 0.0;
#pragma unroll
        for (int k = 0; k < 8; k++) {
            s1 += g_part[t + 256*k];
            s2 += g_part[MM + t + 256*k];
        }
#pragma unroll
        for (int off = 16; off > 0; off >>= 1) {
            s1 += __shfl_down_sync(WALL, s1, off);
            s2 += __shfl_down_sync(WALL, s2, off);
        }
        if (lane == 0) { red1[wid] = s1; red2[wid] = s2; }
        __syncthreads();
        if (t == 0) {
            double a = 0.0, b = 0.0;
#pragma unroll
            for (int k = 0; k < 8; k++) { a += red1[k]; b += red2[k]; }
            out[0] = (float)(sqrt(a) + b / (3.0 * (double)MM));
        }
    }
}

// ---------------- launch ----------------
extern "C" void kernel_launch(void* const* d_in, const int* in_sizes, int n_in,
                              void* d_out, int out_size) {
    const float* acc  = (const float*)d_in[0];
    const float* gyr  = (const float*)d_in[1];
    const float* ab   = (const float*)d_in[2];
    const float* gb   = (const float*)d_in[3];
    const float* dts  = (const float*)d_in[4];
    const float* q0   = (const float*)d_in[5];
    const float* p0   = (const float*)d_in[6];
    const float* v0   = (const float*)d_in[7];
    const float* prot = (const float*)d_in[8];
    const float* ptrn = (const float*)d_in[9];
    const int*   sync = (const int*)d_in[10];

    k_all<<<NBLK, NTHR>>>(acc, gyr, ab, gb, dts, q0, p0, v0,
                          prot, ptrn, sync, (float*)d_out);
}

// round 10
// speedup vs baseline: 1.3174x; 1.3109x over previous
#include <cuda_runtime.h>
#include <math.h>

#define NN 262144
#define LL 64
#define LOG_L 6
#define CC (NN / LL)      // 4096 chunks of 64 steps
#define MM 2048
#define GRAV 9.81007f
#define WALL 0xffffffffu

struct S12 { float4 dq; float Ax,Ay,Az,Px,Py,Pz,T,G; };

__device__ float4 g_s0[CC];      // chunk totals: dq
__device__ float4 g_s1[CC];      // Ax,Ay,Az,T
__device__ float4 g_s2[CC];      // Px,Py,Pz,G
__device__ float4 g_sq[CC];      // chunk-start world rotation
__device__ float  g_sv[3 * CC];
__device__ float  g_sp[3 * CC];
__device__ double g_part[2 * MM];
__device__ unsigned g_ctr = 0;

// ---------------- quaternion helpers ----------------
__device__ __forceinline__ float4 qmul4(float4 q, float4 r) {
    return make_float4(
        q.w*r.x + q.x*r.w + q.y*r.z - q.z*r.y,
        q.w*r.y - q.x*r.z + q.y*r.w + q.z*r.x,
        q.w*r.z + q.x*r.y - q.y*r.x + q.z*r.w,
        q.w*r.w - q.x*r.x - q.y*r.y - q.z*r.z);
}
__device__ __forceinline__ float4 qnorm4(float4 q) {
    float n = rsqrtf(q.x*q.x + q.y*q.y + q.z*q.z + q.w*q.w);
    return make_float4(q.x*n, q.y*n, q.z*n, q.w*n);
}
__device__ __forceinline__ float3 qrot3(float4 q, float3 v) {
    float tx = 2.0f*(q.y*v.z - q.z*v.y);
    float ty = 2.0f*(q.z*v.x - q.x*v.z);
    float tz = 2.0f*(q.x*v.y - q.y*v.x);
    return make_float3(
        v.x + q.w*tx + (q.y*tz - q.z*ty),
        v.y + q.w*ty + (q.z*tx - q.x*tz),
        v.z + q.w*tz + (q.x*ty - q.y*tx));
}

// ---------------- summary algebra ----------------
__device__ __forceinline__ S12 sident() {
    S12 s; s.dq = make_float4(0.f,0.f,0.f,1.f);
    s.Ax=s.Ay=s.Az=s.Px=s.Py=s.Pz=0.f; s.T=s.G=0.f; return s;
}
__device__ __forceinline__ S12 scomb(const S12& a, const S12& b) {
    S12 o;
    o.T = a.T + b.T;
    o.G = a.G + a.T*b.T + b.G;
    float3 rA = qrot3(a.dq, make_float3(b.Ax, b.Ay, b.Az));
    o.Ax = a.Ax + rA.x;  o.Ay = a.Ay + rA.y;  o.Az = a.Az + rA.z;
    float3 rP = qrot3(a.dq, make_float3(b.Px, b.Py, b.Pz));
    o.Px = a.Px + a.Ax*b.T + rP.x;
    o.Py = a.Py + a.Ay*b.T + rP.y;
    o.Pz = a.Pz + a.Az*b.T + rP.z;
    o.dq = qmul4(a.dq, b.dq);
    return o;
}
__device__ __forceinline__ S12 shfl_down_S(const S12& s, int off) {
    S12 r;
    r.dq.x = __shfl_down_sync(WALL, s.dq.x, off);
    r.dq.y = __shfl_down_sync(WALL, s.dq.y, off);
    r.dq.z = __shfl_down_sync(WALL, s.dq.z, off);
    r.dq.w = __shfl_down_sync(WALL, s.dq.w, off);
    r.Ax = __shfl_down_sync(WALL, s.Ax, off);
    r.Ay = __shfl_down_sync(WALL, s.Ay, off);
    r.Az = __shfl_down_sync(WALL, s.Az, off);
    r.Px = __shfl_down_sync(WALL, s.Px, off);
    r.Py = __shfl_down_sync(WALL, s.Py, off);
    r.Pz = __shfl_down_sync(WALL, s.Pz, off);
    r.T  = __shfl_down_sync(WALL, s.T,  off);
    r.G  = __shfl_down_sync(WALL, s.G,  off);
    return r;
}
__device__ __forceinline__ S12 shfl_up_S(const S12& s, int off) {
    S12 r;
    r.dq.x = __shfl_up_sync(WALL, s.dq.x, off);
    r.dq.y = __shfl_up_sync(WALL, s.dq.y, off);
    r.dq.z = __shfl_up_sync(WALL, s.dq.z, off);
    r.dq.w = __shfl_up_sync(WALL, s.dq.w, off);
    r.Ax = __shfl_up_sync(WALL, s.Ax, off);
    r.Ay = __shfl_up_sync(WALL, s.Ay, off);
    r.Az = __shfl_up_sync(WALL, s.Az, off);
    r.Px = __shfl_up_sync(WALL, s.Px, off);
    r.Py = __shfl_up_sync(WALL, s.Py, off);
    r.Pz = __shfl_up_sync(WALL, s.Pz, off);
    r.T  = __shfl_up_sync(WALL, s.T,  off);
    r.G  = __shfl_up_sync(WALL, s.G,  off);
    return r;
}
__device__ __forceinline__ S12 warp_fold(S12 s) {
#pragma unroll
    for (int off = 1; off < 32; off <<= 1) s = scomb(s, shfl_down_S(s, off));
    return s;  // lane 0
}
__device__ __forceinline__ S12 warp_scan(S12 s, int lane) {
#pragma unroll
    for (int off = 1; off < 32; off <<= 1) {
        S12 o = shfl_up_S(s, off);
        if (lane >= off) s = scomb(o, s);
    }
    return s;
}

// per-step summary (Taylor exp_so3; guarded libm fallback)
__device__ __forceinline__ S12 step_reg(float ax, float ay, float az,
                                        float gx, float gy, float gz, float dt,
                                        float abx, float aby, float abz,
                                        float gbx, float gby, float gbz) {
    ax -= abx; ay -= aby; az -= abz;
    float px = (gx - gbx) * dt;
    float py = (gy - gby) * dt;
    float pz = (gz - gbz) * dt;
    float th2 = px*px + py*py + pz*pz;
    float h2 = 0.25f * th2;
    float sc, w;
    if (h2 < 0.04f) {
        sc = 1.0f - h2*(1.0f/6.0f)*(1.0f - h2*0.05f);
        w  = 1.0f - h2*0.5f*(1.0f - h2*(1.0f/12.0f));
    } else {
        float half = sqrtf(h2);
        sc = sinf(half) / half;
        w  = cosf(half);
    }
    float k = 0.5f * sc;
    S12 s;
    s.dq = make_float4(px*k, py*k, pz*k, w);
    float h = 0.5f * dt * dt;
    s.T = dt;  s.G = h;
    s.Ax = ax*dt;  s.Ay = ay*dt;  s.Az = az*dt;
    s.Px = ax*h;   s.Py = ay*h;   s.Pz = az*h;
    return s;
}
__device__ __forceinline__ S12 load_chunk(int c) {
    float4 f0 = g_s0[c], f1 = g_s1[c], f2 = g_s2[c];
    S12 s; s.dq=f0; s.Ax=f1.x; s.Ay=f1.y; s.Az=f1.z; s.T=f1.w;
    s.Px=f2.x; s.Py=f2.y; s.Pz=f2.z; s.G=f2.w;
    return s;
}

// ---------------- kernel 1: chunk summaries (warp/chunk of 64 steps) ----------------
__global__ void __launch_bounds__(256)
k_chunk(const float* __restrict__ acc, const float* __restrict__ gyr,
        const float* __restrict__ ab,  const float* __restrict__ gb,
        const float* __restrict__ dts) {
    int gw   = (blockIdx.x * blockDim.x + threadIdx.x) >> 5;   // chunk id [0, 4096)
    int lane = threadIdx.x & 31;
    float abx = __ldg(&ab[0]), aby = __ldg(&ab[1]), abz = __ldg(&ab[2]);
    float gbx = __ldg(&gb[0]), gby = __ldg(&gb[1]), gbz = __ldg(&gb[2]);
    const float2* acc2 = (const float2*)acc;
    const float2* gyr2 = (const float2*)gyr;
    const float2* dt2  = (const float2*)dts;
    int vb = 96*gw + 3*lane;
    float2 A0 = acc2[vb], A1 = acc2[vb+1], A2 = acc2[vb+2];
    float2 G0 = gyr2[vb], G1 = gyr2[vb+1], G2 = gyr2[vb+2];
    float2 D  = dt2[(gw<<5) + lane];
    S12 s =      step_reg(A0.x,A0.y,A1.x, G0.x,G0.y,G1.x, D.x, abx,aby,abz, gbx,gby,gbz);
    s = scomb(s, step_reg(A1.y,A2.x,A2.y, G1.y,G2.x,G2.y, D.y, abx,aby,abz, gbx,gby,gbz));
    s = warp_fold(s);
    if (lane == 0) {
        s.dq = qnorm4(s.dq);
        g_s0[gw] = s.dq;
        g_s1[gw] = make_float4(s.Ax, s.Ay, s.Az, s.T);
        g_s2[gw] = make_float4(s.Px, s.Py, s.Pz, s.G);
    }
}

// ---------------- kernel 2: block scan of 4096 summaries -> chunk-start states ----------------
__global__ void __launch_bounds__(1024)
k_scan(const float* __restrict__ q0p, const float* __restrict__ p0p,
       const float* __restrict__ v0p) {
    __shared__ S12 shw[32];
    int t = threadIdx.x, lane = t & 31, wid = t >> 5;
    if (t == 0) g_ctr = 0;                 // reset last-block counter for k_sync
    int c0 = 4*t;
    S12 a0 = load_chunk(c0);
    S12 a1 = load_chunk(c0+1);
    S12 a2 = load_chunk(c0+2);
    S12 a3 = load_chunk(c0+3);
    S12 t01 = scomb(a0, a1);
    S12 t23 = scomb(a2, a3);
    S12 tot = scomb(t01, t23);
    S12 inc = warp_scan(tot, lane);
    if (lane == 31) shw[wid] = inc;
    __syncthreads();
    if (wid == 0) shw[lane] = warp_scan(shw[lane], lane);   // full 32-lane warp
    __syncthreads();
    S12 lex = shfl_up_S(inc, 1);
    S12 ex;
    if (wid == 0) ex = (lane == 0) ? sident() : lex;
    else          ex = (lane == 0) ? shw[wid-1] : scomb(shw[wid-1], lex);

    float4 q0 = make_float4(q0p[0], q0p[1], q0p[2], q0p[3]);
    float3 v0 = make_float3(v0p[0], v0p[1], v0p[2]);
    float3 p0 = make_float3(p0p[0], p0p[1], p0p[2]);
#pragma unroll
    for (int k = 0; k < 4; k++) {
        int c = c0 + k;
        float4 qc = qnorm4(qmul4(q0, ex.dq));
        float3 rA = qrot3(q0, make_float3(ex.Ax, ex.Ay, ex.Az));
        float3 rP = qrot3(q0, make_float3(ex.Px, ex.Py, ex.Pz));
        g_sq[c] = qc;
        g_sv[3*c]   = v0.x + rA.x;
        g_sv[3*c+1] = v0.y + rA.y;
        g_sv[3*c+2] = v0.z + rA.z - GRAV * ex.T;
        g_sp[3*c]   = p0.x + v0.x * ex.T + rP.x;
        g_sp[3*c+1] = p0.y + v0.y * ex.T + rP.y;
        g_sp[3*c+2] = p0.z + v0.z * ex.T + rP.z - GRAV * ex.G;
        if (k == 0)      ex = scomb(ex, a0);
        else if (k == 1) ex = scomb(ex, a1);
        else if (k == 2) ex = scomb(ex, a2);
    }
}

// ---------------- kernel 3: sync eval (warp/sync) + fused deterministic reduction ----------------
__global__ void __launch_bounds__(256)
k_sync(const int* __restrict__ sync, const float* __restrict__ prot,
       const float* __restrict__ ptrn,
       const float* __restrict__ acc, const float* __restrict__ gyr,
       const float* __restrict__ ab,  const float* __restrict__ gb,
       const float* __restrict__ dts, float* __restrict__ out) {
    __shared__ double red1[8], red2[8];
    __shared__ bool is_last;
    int gw   = (blockIdx.x * blockDim.x + threadIdx.x) >> 5;   // sync id
    int lane = threadIdx.x & 31;
    int i = sync[gw];
    int c = i >> LOG_L;
    int r = i & (LL - 1);
    float abx = __ldg(&ab[0]), aby = __ldg(&ab[1]), abz = __ldg(&ab[2]);
    float gbx = __ldg(&gb[0]), gby = __ldg(&gb[1]), gbz = __ldg(&gb[2]);
    const float2* acc2 = (const float2*)acc;
    const float2* gyr2 = (const float2*)gyr;
    const float2* dt2  = (const float2*)dts;
    int vb = 96*c + 3*lane;
    S12 s = sident();
    int j0 = 2*lane, j1 = 2*lane + 1;
    if (j0 <= r) {
        float2 A0 = acc2[vb], A1 = acc2[vb+1];
        float2 G0 = gyr2[vb], G1 = gyr2[vb+1];
        float2 D  = dt2[(c<<5) + lane];
        s = step_reg(A0.x,A0.y,A1.x, G0.x,G0.y,G1.x, D.x, abx,aby,abz, gbx,gby,gbz);
        if (j1 <= r) {
            float2 A2 = acc2[vb+2];
            float2 G2 = gyr2[vb+2];
            s = scomb(s, step_reg(A1.y,A2.x,A2.y, G1.y,G2.x,G2.y, D.y, abx,aby,abz, gbx,gby,gbz));
        }
    }
    s = warp_fold(s);
    if (lane == 0) {
        float4 qc = g_sq[c];
        float4 q = qnorm4(qmul4(qc, s.dq));
        float tel = s.T;
        float3 rP = qrot3(qc, make_float3(s.Px, s.Py, s.Pz));
        float Pxx = g_sp[3*c]   + g_sv[3*c]  * tel + rP.x;
        float Pyy = g_sp[3*c+1] + g_sv[3*c+1]* tel + rP.y;
        float Pzz = g_sp[3*c+2] + g_sv[3*c+2]* tel + rP.z - GRAV * s.G;

        float4 pq = make_float4(prot[4*gw], prot[4*gw+1], prot[4*gw+2], prot[4*gw+3]);
        float4 rel = qmul4(make_float4(-pq.x, -pq.y, -pq.z, pq.w), q);
        float nn2 = rel.x*rel.x + rel.y*rel.y + rel.z*rel.z;
        float nn = sqrtf(nn2);
        float theta = 2.0f * atan2f(nn, rel.w);
        float scale = (nn < 1e-7f) ? 2.0f : theta / fmaxf(nn, 1e-12f);
        float lsq = nn2 * scale * scale;

        float dx = ptrn[3*gw+0] - Pxx;
        float dy = ptrn[3*gw+1] - Pyy;
        float dz = ptrn[3*gw+2] - Pzz;
        g_part[gw]      = (double)lsq;
        g_part[MM + gw] = (double)dx*dx + (double)dy*dy + (double)dz*dz;
    }
    // ---- last-block fused reduction (deterministic: fixed slots, fixed tree) ----
    __syncthreads();
    if (threadIdx.x == 0) {
        __threadfence();
        unsigned old = atomicAdd(&g_ctr, 1u);
        is_last = (old == gridDim.x - 1);
    }
    __syncthreads();
    if (!is_last) return;
    int t = threadIdx.x;
    double s1 = 0.0, s2 = 0.0;
#pragma unroll
    for (int k = 0; k < 8; k++) {
        s1 += g_part[t + 256*k];
        s2 += g_part[MM + t + 256*k];
    }
#pragma unroll
    for (int off = 16; off > 0; off >>= 1) {
        s1 += __shfl_down_sync(WALL, s1, off);
        s2 += __shfl_down_sync(WALL, s2, off);
    }
    int wid = t >> 5;
    if ((t & 31) == 0) { red1[wid] = s1; red2[wid] = s2; }
    __syncthreads();
    if (t == 0) {
        double a = 0.0, b = 0.0;
#pragma unroll
        for (int k = 0; k < 8; k++) { a += red1[k]; b += red2[k]; }
        out[0] = (float)(sqrt(a) + b / (3.0 * (double)MM));
    }
}

// ---------------- launch ----------------
extern "C" void kernel_launch(void* const* d_in, const int* in_sizes, int n_in,
                              void* d_out, int out_size) {
    const float* acc  = (const float*)d_in[0];
    const float* gyr  = (const float*)d_in[1];
    const float* ab   = (const float*)d_in[2];
    const float* gb   = (const float*)d_in[3];
    const float* dts  = (const float*)d_in[4];
    const float* q0   = (const float*)d_in[5];
    const float* p0   = (const float*)d_in[6];
    const float* v0   = (const float*)d_in[7];
    const float* prot = (const float*)d_in[8];
    const float* ptrn = (const float*)d_in[9];
    const int*   sync = (const int*)d_in[10];

    k_chunk <<<CC*32/256, 256>>>(acc, gyr, ab, gb, dts);   // 512 CTAs
    k_scan  <<<1, 1024>>>(q0, p0, v0);
    k_sync  <<<MM*32/256, 256>>>(sync, prot, ptrn, acc, gyr, ab, gb, dts, (float*)d_out);
}